// round 12
// baseline (speedup 1.0000x reference)
#include <cuda_runtime.h>
#include <cuda_fp16.h>
#include <math.h>
#include <stdint.h>

#define N_NODES   50000
#define N_EDGES   800000
#define HID       256
#define NUM_GRAPHS 512
#define LEAKY     0.01f
#define LN_EPS    1e-5f

#define SCAN_CH   2048
#define SCAN_NBLK ((N_NODES + SCAN_CH - 1) / SCAN_CH)   // 25

#define NCHUNK    4
#define CHUNK_N   ((N_NODES + NCHUNK - 1) / NCHUNK)     // 12500

// ---------------- device scratch ----------------
__device__ int   g_is64;
__device__ int   g_deg[N_NODES];
__device__ float g_dinv[N_NODES];
__device__ int   g_rowptr[N_NODES + 1];
__device__ int   g_cursor[N_NODES];
__device__ int   g_csr_src[N_EDGES];
__device__ int   g_bsum[SCAN_NBLK];
__device__ int   g_boff[SCAN_NBLK];
__device__ __align__(16) __half g_h16A[(size_t)N_NODES * HID];  // GEMM1 out / agg2 out
__device__ __align__(16) __half g_h16B[(size_t)N_NODES * HID];  // agg1 out
__device__ __align__(16) __half g_h16C[(size_t)N_NODES * HID];  // GEMM2 out
__device__ __align__(16) __half g_Wt1[HID * HID];               // W1^T fp16 [n][k]
__device__ __align__(16) __half g_Wt2[HID * HID];               // W2^T fp16 [n][k]

__device__ __forceinline__ int load_idx(const void* p, long long i, int is64) {
    return is64 ? (int)((const long long*)p)[i] : ((const int*)p)[i];
}

__device__ __forceinline__ void load8h(const __half* p, float* f) {
    uint4 u = *(const uint4*)p;
    const __half2* hp = (const __half2*)&u;
#pragma unroll
    for (int i = 0; i < 4; i++) {
        float2 t = __half22float2(hp[i]);
        f[2 * i] = t.x; f[2 * i + 1] = t.y;
    }
}

// ---------------- W transpose + fp16 convert ----------------
__global__ void k_wconv(const float* __restrict__ W, __half* __restrict__ Wt) {
    int n = blockIdx.x;
    int k = threadIdx.x;
    Wt[n * HID + k] = __float2half_rn(W[(size_t)k * HID + n]);
}

// ---------------- fused: init deg + dtype detect ----------------
__global__ void k_detect_init(const void* edge, int gN) {
    if (blockIdx.x < gN) {
        int i = blockIdx.x * blockDim.x + threadIdx.x;
        if (i < N_NODES) g_deg[i] = 1;
        return;
    }
    __shared__ int any;
    if (threadIdx.x == 0) any = 0;
    __syncthreads();
    const int* w = (const int*)edge;
    int local = 0;
    for (int i = threadIdx.x; i < 1024; i += blockDim.x)
        if (w[2 * i + 1] != 0) local = 1;
    if (local) atomicOr(&any, 1);
    __syncthreads();
    if (threadIdx.x == 0) g_is64 = (any == 0) ? 1 : 0;
}

__global__ void k_count(const void* edge) {
    int e = blockIdx.x * blockDim.x + threadIdx.x;
    if (e >= N_EDGES) return;
    int is64 = g_is64;
    int d = load_idx(edge, (long long)N_EDGES + e, is64);
    atomicAdd(&g_deg[d], 1);
}

// ---------------- parallel 3-pass scan ----------------
__global__ void __launch_bounds__(1024) k_scan1() {
    __shared__ int wsum[32];
    int b    = blockIdx.x;
    int tid  = threadIdx.x;
    int lane = tid & 31;
    int wid  = tid >> 5;

    int i0 = b * SCAN_CH + tid * 2;
    int d0 = (i0     < N_NODES) ? g_deg[i0]     : 1;
    int d1 = (i0 + 1 < N_NODES) ? g_deg[i0 + 1] : 1;
    int v0 = (i0     < N_NODES) ? (d0 - 1) : 0;
    int v1 = (i0 + 1 < N_NODES) ? (d1 - 1) : 0;
    int v = v0 + v1;

    int x = v;
#pragma unroll
    for (int off = 1; off < 32; off <<= 1) {
        int t = __shfl_up_sync(0xffffffff, x, off);
        if (lane >= off) x += t;
    }
    if (lane == 31) wsum[wid] = x;
    __syncthreads();
    if (wid == 0) {
        int y = wsum[lane];
#pragma unroll
        for (int off = 1; off < 32; off <<= 1) {
            int t = __shfl_up_sync(0xffffffff, y, off);
            if (lane >= off) y += t;
        }
        wsum[lane] = y;
    }
    __syncthreads();

    int base = (wid ? wsum[wid - 1] : 0) + x - v;
    if (i0 < N_NODES) {
        g_rowptr[i0] = base;
        g_dinv[i0]   = rsqrtf((float)d0);
    }
    if (i0 + 1 < N_NODES) {
        g_rowptr[i0 + 1] = base + v0;
        g_dinv[i0 + 1]   = rsqrtf((float)d1);
    }
    if (tid == 0) g_bsum[b] = 0;
    __syncthreads();
    if (tid == 1023) g_bsum[b] = wsum[31];
}

__global__ void k_scan2() {
    int lane = threadIdx.x;
    int v = (lane < SCAN_NBLK) ? g_bsum[lane] : 0;
    int x = v;
#pragma unroll
    for (int off = 1; off < 32; off <<= 1) {
        int t = __shfl_up_sync(0xffffffff, x, off);
        if (lane >= off) x += t;
    }
    if (lane < SCAN_NBLK) g_boff[lane] = x - v;
    if (lane == 31) g_rowptr[N_NODES] = x;
}

__global__ void k_scan3() {
    int i = blockIdx.x * blockDim.x + threadIdx.x;
    if (i >= N_NODES) return;
    int off = g_boff[i / SCAN_CH];
    int r = g_rowptr[i] + off;
    g_rowptr[i] = r;
    g_cursor[i] = r;
}

__global__ void k_scatter(const void* edge) {
    int e = blockIdx.x * blockDim.x + threadIdx.x;
    if (e >= N_EDGES) return;
    int is64 = g_is64;
    int srce = load_idx(edge, e, is64);
    int dste = load_idx(edge, (long long)N_EDGES + e, is64);
    int pos = atomicAdd(&g_cursor[dste], 1);
    g_csr_src[pos] = srce;
}

// ---------------- fp16 tensor-core GEMM: C[M,256](fp16) = A @ Wt^T -------
#define BM 128
#define BN 128
#define BK 16
#define KPAD 24

__device__ __forceinline__ void mma_f16(float* c, const uint32_t* a, const uint32_t* b) {
    asm volatile(
        "mma.sync.aligned.m16n8k16.row.col.f32.f16.f16.f32 "
        "{%0,%1,%2,%3}, {%4,%5,%6,%7}, {%8,%9}, {%0,%1,%2,%3};"
        : "+f"(c[0]), "+f"(c[1]), "+f"(c[2]), "+f"(c[3])
        : "r"(a[0]), "r"(a[1]), "r"(a[2]), "r"(a[3]), "r"(b[0]), "r"(b[1]));
}

__device__ __forceinline__ uint4 ldA8(const float* A, size_t off) {
    float4 f0 = *(const float4*)(A + off);
    float4 f1 = *(const float4*)(A + off + 4);
    __half2 h0 = __floats2half2_rn(f0.x, f0.y);
    __half2 h1 = __floats2half2_rn(f0.z, f0.w);
    __half2 h2 = __floats2half2_rn(f1.x, f1.y);
    __half2 h3 = __floats2half2_rn(f1.z, f1.w);
    uint4 r;
    r.x = *(uint32_t*)&h0; r.y = *(uint32_t*)&h1;
    r.z = *(uint32_t*)&h2; r.w = *(uint32_t*)&h3;
    return r;
}
__device__ __forceinline__ uint4 ldA8(const __half* A, size_t off) {
    return *(const uint4*)(A + off);
}

template <typename AT>
__global__ void __launch_bounds__(256)
k_gemm(const AT* __restrict__ A, const __half* __restrict__ Wt,
       __half* __restrict__ C, int M) {
    __shared__ __half As[2][BM][KPAD];
    __shared__ __half Bs[2][BN][KPAD];

    int tid  = threadIdx.x;
    int lane = tid & 31;
    int wid  = tid >> 5;
    int gid  = lane >> 2;
    int tig  = lane & 3;
    int wm = (wid & 1) * 64;
    int wn = (wid >> 1) * 32;
    int m0 = blockIdx.x * BM;
    int n0 = blockIdx.y * BN;

    int srow = tid >> 1;
    int sk8  = (tid & 1) * 8;

    float acc[4][4][4];
#pragma unroll
    for (int i = 0; i < 4; i++)
#pragma unroll
        for (int j = 0; j < 4; j++)
#pragma unroll
            for (int r = 0; r < 4; r++) acc[i][j][r] = 0.f;

    uint4 pa, pb;
    {
        int m = m0 + srow;
        pa = (m < M) ? ldA8(A, (size_t)m * 256 + sk8)
                     : make_uint4(0u, 0u, 0u, 0u);
        pb = *(const uint4*)&Wt[(size_t)(n0 + srow) * 256 + sk8];
    }
    *(uint4*)&As[0][srow][sk8] = pa;
    *(uint4*)&Bs[0][srow][sk8] = pb;
    __syncthreads();

    int buf = 0;
    for (int k0 = 0; k0 < 256; k0 += BK) {
        bool has_next = (k0 + BK) < 256;
        if (has_next) {
            int kb = k0 + BK;
            int m = m0 + srow;
            pa = (m < M) ? ldA8(A, (size_t)m * 256 + kb + sk8)
                         : make_uint4(0u, 0u, 0u, 0u);
            pb = *(const uint4*)&Wt[(size_t)(n0 + srow) * 256 + kb + sk8];
        }

        uint32_t af[4][4];
        uint32_t bf[4][2];
#pragma unroll
        for (int mt = 0; mt < 4; mt++) {
            int r0 = wm + mt * 16 + gid;
            af[mt][0] = *(const uint32_t*)&As[buf][r0][2 * tig];
            af[mt][1] = *(const uint32_t*)&As[buf][r0 + 8][2 * tig];
            af[mt][2] = *(const uint32_t*)&As[buf][r0][2 * tig + 8];
            af[mt][3] = *(const uint32_t*)&As[buf][r0 + 8][2 * tig + 8];
        }
#pragma unroll
        for (int nt = 0; nt < 4; nt++) {
            int c0 = wn + nt * 8 + gid;
            bf[nt][0] = *(const uint32_t*)&Bs[buf][c0][2 * tig];
            bf[nt][1] = *(const uint32_t*)&Bs[buf][c0][2 * tig + 8];
        }
#pragma unroll
        for (int mt = 0; mt < 4; mt++)
#pragma unroll
            for (int nt = 0; nt < 4; nt++)
                mma_f16(acc[mt][nt], af[mt], bf[nt]);

        if (has_next) {
            int nb = buf ^ 1;
            *(uint4*)&As[nb][srow][sk8] = pa;
            *(uint4*)&Bs[nb][srow][sk8] = pb;
            __syncthreads();
            buf = nb;
        }
    }

#pragma unroll
    for (int mt = 0; mt < 4; mt++) {
#pragma unroll
        for (int nt = 0; nt < 4; nt++) {
            int r0 = m0 + wm + mt * 16 + gid;
            int col = n0 + wn + nt * 8 + tig * 2;
            if (r0 < M)
                *(__half2*)&C[(size_t)r0 * 256 + col] =
                    __floats2half2_rn(acc[mt][nt][0], acc[mt][nt][1]);
            if (r0 + 8 < M)
                *(__half2*)&C[(size_t)(r0 + 8) * 256 + col] =
                    __floats2half2_rn(acc[mt][nt][2], acc[mt][nt][3]);
        }
    }
}

// ---------------- fused aggregate + bias + LayerNorm + LeakyReLU ----------
// processes nodes [node0, node0 + n_nodes)
__global__ void k_agg_ln(const __half* __restrict__ h, __half* __restrict__ out,
                         const float* __restrict__ bias,
                         const float* __restrict__ lnw,
                         const float* __restrict__ lnb,
                         int node0, int n_nodes) {
    int widx = (blockIdx.x * blockDim.x + threadIdx.x) >> 5;
    int lane = threadIdx.x & 31;
    if (widx >= n_nodes) return;
    int node = node0 + widx;
    int f0 = lane * 8;

    float di = g_dinv[node];
    float ws = di * di;

    float acc[4][8];
    {
        float sf[8];
        load8h(h + (size_t)node * HID + f0, sf);
#pragma unroll
        for (int i = 0; i < 8; i++) acc[0][i] = sf[i] * ws;
#pragma unroll
        for (int u = 1; u < 4; u++)
#pragma unroll
            for (int i = 0; i < 8; i++) acc[u][i] = 0.f;
    }

    int beg = g_rowptr[node];
    int end = g_rowptr[node + 1];
    int e = beg;
    for (; e + 3 < end; e += 4) {
        int s0 = g_csr_src[e];
        int s1 = g_csr_src[e + 1];
        int s2 = g_csr_src[e + 2];
        int s3 = g_csr_src[e + 3];
        float w0 = g_dinv[s0] * di;
        float w1 = g_dinv[s1] * di;
        float w2 = g_dinv[s2] * di;
        float w3 = g_dinv[s3] * di;
        float r0[8], r1[8], r2[8], r3[8];
        load8h(h + (size_t)s0 * HID + f0, r0);
        load8h(h + (size_t)s1 * HID + f0, r1);
        load8h(h + (size_t)s2 * HID + f0, r2);
        load8h(h + (size_t)s3 * HID + f0, r3);
#pragma unroll
        for (int i = 0; i < 8; i++) {
            acc[0][i] += r0[i] * w0;
            acc[1][i] += r1[i] * w1;
            acc[2][i] += r2[i] * w2;
            acc[3][i] += r3[i] * w3;
        }
    }
    for (; e < end; e++) {
        int s = g_csr_src[e];
        float wv = g_dinv[s] * di;
        float r[8];
        load8h(h + (size_t)s * HID + f0, r);
#pragma unroll
        for (int i = 0; i < 8; i++) acc[0][i] += r[i] * wv;
    }

    float a[8];
#pragma unroll
    for (int i = 0; i < 8; i++)
        a[i] = (acc[0][i] + acc[1][i]) + (acc[2][i] + acc[3][i]);

    float4 b0 = ((const float4*)bias)[lane * 2];
    float4 b1 = ((const float4*)bias)[lane * 2 + 1];
    a[0] += b0.x; a[1] += b0.y; a[2] += b0.z; a[3] += b0.w;
    a[4] += b1.x; a[5] += b1.y; a[6] += b1.z; a[7] += b1.w;

    float sum = 0.f;
#pragma unroll
    for (int i = 0; i < 8; i++) sum += a[i];
#pragma unroll
    for (int off = 16; off > 0; off >>= 1)
        sum += __shfl_xor_sync(0xffffffff, sum, off);
    float mu = sum * (1.0f / HID);

    float d[8], sq = 0.f;
#pragma unroll
    for (int i = 0; i < 8; i++) { d[i] = a[i] - mu; sq += d[i] * d[i]; }
#pragma unroll
    for (int off = 16; off > 0; off >>= 1)
        sq += __shfl_xor_sync(0xffffffff, sq, off);
    float inv = rsqrtf(sq * (1.0f / HID) + LN_EPS);

    float4 w0 = ((const float4*)lnw)[lane * 2];
    float4 w1 = ((const float4*)lnw)[lane * 2 + 1];
    float4 lb0 = ((const float4*)lnb)[lane * 2];
    float4 lb1 = ((const float4*)lnb)[lane * 2 + 1];
    float lw[8] = {w0.x, w0.y, w0.z, w0.w, w1.x, w1.y, w1.z, w1.w};
    float lb[8] = {lb0.x, lb0.y, lb0.z, lb0.w, lb1.x, lb1.y, lb1.z, lb1.w};

    __half2 o[4];
#pragma unroll
    for (int i = 0; i < 4; i++) {
        float t0 = d[2 * i]     * inv * lw[2 * i]     + lb[2 * i];
        float t1 = d[2 * i + 1] * inv * lw[2 * i + 1] + lb[2 * i + 1];
        t0 = (t0 >= 0.f) ? t0 : LEAKY * t0;
        t1 = (t1 >= 0.f) ? t1 : LEAKY * t1;
        o[i] = __floats2half2_rn(t0, t1);
    }
    *(uint4*)(out + (size_t)node * HID + f0) = *(uint4*)o;
}

// ---------------- per-graph mean pool (fp16 input) ----------------
__global__ void k_pool(const __half* __restrict__ h, const void* batch,
                       float* __restrict__ out) {
    int g = blockIdx.x;
    int is64 = g_is64;

    int lo = 0, hi = N_NODES;
    while (lo < hi) {
        int mid = (lo + hi) >> 1;
        if (load_idx(batch, mid, is64) < g) lo = mid + 1; else hi = mid;
    }
    int start = lo;
    hi = N_NODES;
    while (lo < hi) {
        int mid = (lo + hi) >> 1;
        if (load_idx(batch, mid, is64) < g + 1) lo = mid + 1; else hi = mid;
    }
    int end = lo;

    int t = threadIdx.x;
    float a0 = 0.f, a1 = 0.f, a2 = 0.f, a3 = 0.f;
    int i = start;
    for (; i + 3 < end; i += 4) {
        a0 += __half2float(h[(size_t)(i + 0) * HID + t]);
        a1 += __half2float(h[(size_t)(i + 1) * HID + t]);
        a2 += __half2float(h[(size_t)(i + 2) * HID + t]);
        a3 += __half2float(h[(size_t)(i + 3) * HID + t]);
    }
    for (; i < end; i++) a0 += __half2float(h[(size_t)i * HID + t]);
    float acc = (a0 + a1) + (a2 + a3);
    float cnt = (float)(end - start);
    out[(size_t)g * HID + t] = acc / fmaxf(cnt, 1.f);
}

// ---------------- launch ----------------
extern "C" void kernel_launch(void* const* d_in, const int* in_sizes, int n_in,
                              void* d_out, int out_size) {
    const float* x    = (const float*)d_in[0];
    const void*  edge = d_in[1];
    const void*  batch= d_in[2];
    const float* W1   = (const float*)d_in[3];
    const float* b1   = (const float*)d_in[4];
    const float* ln1w = (const float*)d_in[5];
    const float* ln1b = (const float*)d_in[6];
    const float* W2   = (const float*)d_in[7];
    const float* b2   = (const float*)d_in[8];
    const float* ln2w = (const float*)d_in[9];
    const float* ln2b = (const float*)d_in[10];
    float* out = (float*)d_out;

    __half *hA = nullptr, *hB = nullptr, *hC = nullptr, *Wt1 = nullptr, *Wt2 = nullptr;
    cudaGetSymbolAddress((void**)&hA, g_h16A);
    cudaGetSymbolAddress((void**)&hB, g_h16B);
    cudaGetSymbolAddress((void**)&hC, g_h16C);
    cudaGetSymbolAddress((void**)&Wt1, g_Wt1);
    cudaGetSymbolAddress((void**)&Wt2, g_Wt2);

    static cudaStream_t s_side = nullptr;
    static cudaEvent_t  s_fork = nullptr, s_join = nullptr, s_join2 = nullptr;
    static cudaEvent_t  s_ck[NCHUNK] = {};
    static int s_ok = -1;
    if (s_ok < 0) {
        s_ok = 1;
        if (cudaStreamCreateWithFlags(&s_side, cudaStreamNonBlocking) != cudaSuccess) s_ok = 0;
        if (s_ok && cudaEventCreateWithFlags(&s_fork, cudaEventDisableTiming) != cudaSuccess) s_ok = 0;
        if (s_ok && cudaEventCreateWithFlags(&s_join, cudaEventDisableTiming) != cudaSuccess) s_ok = 0;
        if (s_ok && cudaEventCreateWithFlags(&s_join2, cudaEventDisableTiming) != cudaSuccess) s_ok = 0;
        for (int c = 0; c < NCHUNK && s_ok; c++)
            if (cudaEventCreateWithFlags(&s_ck[c], cudaEventDisableTiming) != cudaSuccess) s_ok = 0;
    }
    cudaStream_t side = s_ok ? s_side : (cudaStream_t)0;

    const int TB = 256;
    int gN = (N_NODES + TB - 1) / TB;
    int gE = (N_EDGES + TB - 1) / TB;

    dim3 gemmGrid((N_NODES + BM - 1) / BM, 256 / BN);   // (391, 2)
    int aggBlocksFull = (N_NODES * 32 + TB - 1) / TB;

    if (s_ok) {
        cudaEventRecord(s_fork, 0);
        cudaStreamWaitEvent(side, s_fork, 0);
    }

    // main stream: W1 convert, GEMM1
    k_wconv<<<HID, HID>>>(W1, Wt1);
    k_gemm<float><<<gemmGrid, TB>>>(x, Wt1, hA, N_NODES);

    // side stream: CSR build + W2 convert
    k_detect_init<<<gN + 1, TB, 0, side>>>(edge, gN);
    k_count<<<gE, TB, 0, side>>>(edge);
    k_scan1<<<SCAN_NBLK, 1024, 0, side>>>();
    k_scan2<<<1, 32, 0, side>>>();
    k_scan3<<<gN, TB, 0, side>>>();
    k_scatter<<<gE, TB, 0, side>>>(edge);
    k_wconv<<<HID, HID, 0, side>>>(W2, Wt2);

    if (s_ok) {
        cudaEventRecord(s_join, side);
        cudaStreamWaitEvent(0, s_join, 0);
    }

    // chunked pipeline: agg1 chunk c (main) -> GEMM2 chunk c (side)
    for (int c = 0; c < NCHUNK; c++) {
        int node0 = c * CHUNK_N;
        int cnt = N_NODES - node0;
        if (cnt > CHUNK_N) cnt = CHUNK_N;
        int aggBlocks = (cnt * 32 + TB - 1) / TB;
        k_agg_ln<<<aggBlocks, TB>>>(hA, hB, b1, ln1w, ln1b, node0, cnt);
        if (s_ok) {
            cudaEventRecord(s_ck[c], 0);
            cudaStreamWaitEvent(side, s_ck[c], 0);
            dim3 g2((cnt + BM - 1) / BM, 256 / BN);
            k_gemm<__half><<<g2, TB, 0, side>>>(hB + (size_t)node0 * 256, Wt2,
                                                hC + (size_t)node0 * 256, cnt);
        }
    }
    if (!s_ok) {
        // fallback: serial GEMM2 on default stream
        k_gemm<__half><<<gemmGrid, TB>>>(hB, Wt2, hC, N_NODES);
    } else {
        cudaEventRecord(s_join2, side);
        cudaStreamWaitEvent(0, s_join2, 0);
    }

    // agg2 (gather hC -> hA), then pool
    k_agg_ln<<<aggBlocksFull, TB>>>(hC, hA, b2, ln2w, ln2b, 0, N_NODES);
    k_pool<<<NUM_GRAPHS, HID>>>(hA, batch, out);
}

// round 13
// speedup vs baseline: 1.0706x; 1.0706x over previous
#include <cuda_runtime.h>
#include <cuda_fp16.h>
#include <math.h>
#include <stdint.h>

#define N_NODES   50000
#define N_EDGES   800000
#define HID       256
#define NUM_GRAPHS 512
#define LEAKY     0.01f
#define LN_EPS    1e-5f

#define SCAN_CH   2048
#define SCAN_NBLK ((N_NODES + SCAN_CH - 1) / SCAN_CH)   // 25

// ---------------- device scratch ----------------
__device__ int   g_is64;
__device__ int   g_deg[N_NODES];
__device__ float g_dinv[N_NODES];
__device__ int   g_rowptr[N_NODES + 1];
__device__ int   g_cursor[N_NODES];
__device__ int   g_csr_src[N_EDGES];
__device__ float g_csr_w[N_EDGES];                              // dinv[s]*dinv[d]
__device__ int   g_bsum[SCAN_NBLK];
__device__ int   g_boff[SCAN_NBLK];
__device__ __align__(16) __half g_h16A[(size_t)N_NODES * HID];  // GEMM out
__device__ __align__(16) __half g_h16B[(size_t)N_NODES * HID];  // agg out
__device__ __align__(16) __half g_Wt1[HID * HID];               // W1^T fp16 [n][k]
__device__ __align__(16) __half g_Wt2[HID * HID];               // W2^T fp16 [n][k]

__device__ __forceinline__ int load_idx(const void* p, long long i, int is64) {
    return is64 ? (int)((const long long*)p)[i] : ((const int*)p)[i];
}

__device__ __forceinline__ void load8h(const __half* p, float* f) {
    uint4 u = *(const uint4*)p;
    const __half2* hp = (const __half2*)&u;
#pragma unroll
    for (int i = 0; i < 4; i++) {
        float2 t = __half22float2(hp[i]);
        f[2 * i] = t.x; f[2 * i + 1] = t.y;
    }
}

// ---------------- W transpose + fp16 convert ----------------
__global__ void k_wconv(const float* __restrict__ W, __half* __restrict__ Wt) {
    int n = blockIdx.x;
    int k = threadIdx.x;
    Wt[n * HID + k] = __float2half_rn(W[(size_t)k * HID + n]);
}

// ---------------- fused: init deg + dtype detect ----------------
__global__ void k_detect_init(const void* edge, int gN) {
    if (blockIdx.x < gN) {
        int i = blockIdx.x * blockDim.x + threadIdx.x;
        if (i < N_NODES) g_deg[i] = 1;
        return;
    }
    __shared__ int any;
    if (threadIdx.x == 0) any = 0;
    __syncthreads();
    const int* w = (const int*)edge;
    int local = 0;
    for (int i = threadIdx.x; i < 1024; i += blockDim.x)
        if (w[2 * i + 1] != 0) local = 1;
    if (local) atomicOr(&any, 1);
    __syncthreads();
    if (threadIdx.x == 0) g_is64 = (any == 0) ? 1 : 0;
}

__global__ void k_count(const void* edge) {
    int e = blockIdx.x * blockDim.x + threadIdx.x;
    if (e >= N_EDGES) return;
    int is64 = g_is64;
    int d = load_idx(edge, (long long)N_EDGES + e, is64);
    atomicAdd(&g_deg[d], 1);
}

// ---------------- parallel 3-pass scan ----------------
__global__ void __launch_bounds__(1024) k_scan1() {
    __shared__ int wsum[32];
    int b    = blockIdx.x;
    int tid  = threadIdx.x;
    int lane = tid & 31;
    int wid  = tid >> 5;

    int i0 = b * SCAN_CH + tid * 2;
    int d0 = (i0     < N_NODES) ? g_deg[i0]     : 1;
    int d1 = (i0 + 1 < N_NODES) ? g_deg[i0 + 1] : 1;
    int v0 = (i0     < N_NODES) ? (d0 - 1) : 0;
    int v1 = (i0 + 1 < N_NODES) ? (d1 - 1) : 0;
    int v = v0 + v1;

    int x = v;
#pragma unroll
    for (int off = 1; off < 32; off <<= 1) {
        int t = __shfl_up_sync(0xffffffff, x, off);
        if (lane >= off) x += t;
    }
    if (lane == 31) wsum[wid] = x;
    __syncthreads();
    if (wid == 0) {
        int y = wsum[lane];
#pragma unroll
        for (int off = 1; off < 32; off <<= 1) {
            int t = __shfl_up_sync(0xffffffff, y, off);
            if (lane >= off) y += t;
        }
        wsum[lane] = y;
    }
    __syncthreads();

    int base = (wid ? wsum[wid - 1] : 0) + x - v;
    if (i0 < N_NODES) {
        g_rowptr[i0] = base;
        g_dinv[i0]   = rsqrtf((float)d0);
    }
    if (i0 + 1 < N_NODES) {
        g_rowptr[i0 + 1] = base + v0;
        g_dinv[i0 + 1]   = rsqrtf((float)d1);
    }
    if (tid == 0) g_bsum[b] = 0;
    __syncthreads();
    if (tid == 1023) g_bsum[b] = wsum[31];
}

__global__ void k_scan2() {
    int lane = threadIdx.x;
    int v = (lane < SCAN_NBLK) ? g_bsum[lane] : 0;
    int x = v;
#pragma unroll
    for (int off = 1; off < 32; off <<= 1) {
        int t = __shfl_up_sync(0xffffffff, x, off);
        if (lane >= off) x += t;
    }
    if (lane < SCAN_NBLK) g_boff[lane] = x - v;
    if (lane == 31) g_rowptr[N_NODES] = x;
}

__global__ void k_scan3() {
    int i = blockIdx.x * blockDim.x + threadIdx.x;
    if (i >= N_NODES) return;
    int off = g_boff[i / SCAN_CH];
    int r = g_rowptr[i] + off;
    g_rowptr[i] = r;
    g_cursor[i] = r;
}

// scatter also precomputes the edge weight (dinv is ready by now)
__global__ void k_scatter(const void* edge) {
    int e = blockIdx.x * blockDim.x + threadIdx.x;
    if (e >= N_EDGES) return;
    int is64 = g_is64;
    int srce = load_idx(edge, e, is64);
    int dste = load_idx(edge, (long long)N_EDGES + e, is64);
    int pos = atomicAdd(&g_cursor[dste], 1);
    g_csr_src[pos] = srce;
    g_csr_w[pos]   = g_dinv[srce] * g_dinv[dste];
}

// ---------------- fp16 tensor-core GEMM: C[M,256](fp16) = A @ Wt^T -------
#define BM 128
#define BN 128
#define BK 16
#define KPAD 24

__device__ __forceinline__ void mma_f16(float* c, const uint32_t* a, const uint32_t* b) {
    asm volatile(
        "mma.sync.aligned.m16n8k16.row.col.f32.f16.f16.f32 "
        "{%0,%1,%2,%3}, {%4,%5,%6,%7}, {%8,%9}, {%0,%1,%2,%3};"
        : "+f"(c[0]), "+f"(c[1]), "+f"(c[2]), "+f"(c[3])
        : "r"(a[0]), "r"(a[1]), "r"(a[2]), "r"(a[3]), "r"(b[0]), "r"(b[1]));
}

__device__ __forceinline__ uint4 ldA8(const float* A, size_t off) {
    float4 f0 = *(const float4*)(A + off);
    float4 f1 = *(const float4*)(A + off + 4);
    __half2 h0 = __floats2half2_rn(f0.x, f0.y);
    __half2 h1 = __floats2half2_rn(f0.z, f0.w);
    __half2 h2 = __floats2half2_rn(f1.x, f1.y);
    __half2 h3 = __floats2half2_rn(f1.z, f1.w);
    uint4 r;
    r.x = *(uint32_t*)&h0; r.y = *(uint32_t*)&h1;
    r.z = *(uint32_t*)&h2; r.w = *(uint32_t*)&h3;
    return r;
}
__device__ __forceinline__ uint4 ldA8(const __half* A, size_t off) {
    return *(const uint4*)(A + off);
}

template <typename AT>
__global__ void __launch_bounds__(256)
k_gemm(const AT* __restrict__ A, const __half* __restrict__ Wt,
       __half* __restrict__ C, int M) {
    __shared__ __half As[2][BM][KPAD];
    __shared__ __half Bs[2][BN][KPAD];

    int tid  = threadIdx.x;
    int lane = tid & 31;
    int wid  = tid >> 5;
    int gid  = lane >> 2;
    int tig  = lane & 3;
    int wm = (wid & 1) * 64;
    int wn = (wid >> 1) * 32;
    int m0 = blockIdx.x * BM;
    int n0 = blockIdx.y * BN;

    int srow = tid >> 1;
    int sk8  = (tid & 1) * 8;

    float acc[4][4][4];
#pragma unroll
    for (int i = 0; i < 4; i++)
#pragma unroll
        for (int j = 0; j < 4; j++)
#pragma unroll
            for (int r = 0; r < 4; r++) acc[i][j][r] = 0.f;

    uint4 pa, pb;
    {
        int m = m0 + srow;
        pa = (m < M) ? ldA8(A, (size_t)m * 256 + sk8)
                     : make_uint4(0u, 0u, 0u, 0u);
        pb = *(const uint4*)&Wt[(size_t)(n0 + srow) * 256 + sk8];
    }
    *(uint4*)&As[0][srow][sk8] = pa;
    *(uint4*)&Bs[0][srow][sk8] = pb;
    __syncthreads();

    int buf = 0;
    for (int k0 = 0; k0 < 256; k0 += BK) {
        bool has_next = (k0 + BK) < 256;
        if (has_next) {
            int kb = k0 + BK;
            int m = m0 + srow;
            pa = (m < M) ? ldA8(A, (size_t)m * 256 + kb + sk8)
                         : make_uint4(0u, 0u, 0u, 0u);
            pb = *(const uint4*)&Wt[(size_t)(n0 + srow) * 256 + kb + sk8];
        }

        uint32_t af[4][4];
        uint32_t bf[4][2];
#pragma unroll
        for (int mt = 0; mt < 4; mt++) {
            int r0 = wm + mt * 16 + gid;
            af[mt][0] = *(const uint32_t*)&As[buf][r0][2 * tig];
            af[mt][1] = *(const uint32_t*)&As[buf][r0 + 8][2 * tig];
            af[mt][2] = *(const uint32_t*)&As[buf][r0][2 * tig + 8];
            af[mt][3] = *(const uint32_t*)&As[buf][r0 + 8][2 * tig + 8];
        }
#pragma unroll
        for (int nt = 0; nt < 4; nt++) {
            int c0 = wn + nt * 8 + gid;
            bf[nt][0] = *(const uint32_t*)&Bs[buf][c0][2 * tig];
            bf[nt][1] = *(const uint32_t*)&Bs[buf][c0][2 * tig + 8];
        }
#pragma unroll
        for (int mt = 0; mt < 4; mt++)
#pragma unroll
            for (int nt = 0; nt < 4; nt++)
                mma_f16(acc[mt][nt], af[mt], bf[nt]);

        if (has_next) {
            int nb = buf ^ 1;
            *(uint4*)&As[nb][srow][sk8] = pa;
            *(uint4*)&Bs[nb][srow][sk8] = pb;
            __syncthreads();
            buf = nb;
        }
    }

#pragma unroll
    for (int mt = 0; mt < 4; mt++) {
#pragma unroll
        for (int nt = 0; nt < 4; nt++) {
            int r0 = m0 + wm + mt * 16 + gid;
            int col = n0 + wn + nt * 8 + tig * 2;
            if (r0 < M)
                *(__half2*)&C[(size_t)r0 * 256 + col] =
                    __floats2half2_rn(acc[mt][nt][0], acc[mt][nt][1]);
            if (r0 + 8 < M)
                *(__half2*)&C[(size_t)(r0 + 8) * 256 + col] =
                    __floats2half2_rn(acc[mt][nt][2], acc[mt][nt][3]);
        }
    }
}

// ---------------- fused aggregate + bias + LayerNorm + LeakyReLU ----------
// fp16 in/out, 4-way edge unroll; edge weights precomputed (coalesced).
__global__ void k_agg_ln(const __half* __restrict__ h, __half* __restrict__ out,
                         const float* __restrict__ bias,
                         const float* __restrict__ lnw,
                         const float* __restrict__ lnb) {
    int warp = (blockIdx.x * blockDim.x + threadIdx.x) >> 5;
    int lane = threadIdx.x & 31;
    if (warp >= N_NODES) return;
    int node = warp;
    int f0 = lane * 8;

    float di = g_dinv[node];
    float ws = di * di;

    float acc[4][8];
    {
        float sf[8];
        load8h(h + (size_t)node * HID + f0, sf);
#pragma unroll
        for (int i = 0; i < 8; i++) acc[0][i] = sf[i] * ws;
#pragma unroll
        for (int u = 1; u < 4; u++)
#pragma unroll
            for (int i = 0; i < 8; i++) acc[u][i] = 0.f;
    }

    int beg = g_rowptr[node];
    int end = g_rowptr[node + 1];
    int e = beg;
    for (; e + 3 < end; e += 4) {
        int s0 = g_csr_src[e];
        int s1 = g_csr_src[e + 1];
        int s2 = g_csr_src[e + 2];
        int s3 = g_csr_src[e + 3];
        float w0 = g_csr_w[e];
        float w1 = g_csr_w[e + 1];
        float w2 = g_csr_w[e + 2];
        float w3 = g_csr_w[e + 3];
        float r0[8], r1[8], r2[8], r3[8];
        load8h(h + (size_t)s0 * HID + f0, r0);
        load8h(h + (size_t)s1 * HID + f0, r1);
        load8h(h + (size_t)s2 * HID + f0, r2);
        load8h(h + (size_t)s3 * HID + f0, r3);
#pragma unroll
        for (int i = 0; i < 8; i++) {
            acc[0][i] += r0[i] * w0;
            acc[1][i] += r1[i] * w1;
            acc[2][i] += r2[i] * w2;
            acc[3][i] += r3[i] * w3;
        }
    }
    for (; e < end; e++) {
        int s = g_csr_src[e];
        float wv = g_csr_w[e];
        float r[8];
        load8h(h + (size_t)s * HID + f0, r);
#pragma unroll
        for (int i = 0; i < 8; i++) acc[0][i] += r[i] * wv;
    }

    float a[8];
#pragma unroll
    for (int i = 0; i < 8; i++)
        a[i] = (acc[0][i] + acc[1][i]) + (acc[2][i] + acc[3][i]);

    float4 b0 = ((const float4*)bias)[lane * 2];
    float4 b1 = ((const float4*)bias)[lane * 2 + 1];
    a[0] += b0.x; a[1] += b0.y; a[2] += b0.z; a[3] += b0.w;
    a[4] += b1.x; a[5] += b1.y; a[6] += b1.z; a[7] += b1.w;

    float sum = 0.f;
#pragma unroll
    for (int i = 0; i < 8; i++) sum += a[i];
#pragma unroll
    for (int off = 16; off > 0; off >>= 1)
        sum += __shfl_xor_sync(0xffffffff, sum, off);
    float mu = sum * (1.0f / HID);

    float d[8], sq = 0.f;
#pragma unroll
    for (int i = 0; i < 8; i++) { d[i] = a[i] - mu; sq += d[i] * d[i]; }
#pragma unroll
    for (int off = 16; off > 0; off >>= 1)
        sq += __shfl_xor_sync(0xffffffff, sq, off);
    float inv = rsqrtf(sq * (1.0f / HID) + LN_EPS);

    float4 w0 = ((const float4*)lnw)[lane * 2];
    float4 w1 = ((const float4*)lnw)[lane * 2 + 1];
    float4 lb0 = ((const float4*)lnb)[lane * 2];
    float4 lb1 = ((const float4*)lnb)[lane * 2 + 1];
    float lw[8] = {w0.x, w0.y, w0.z, w0.w, w1.x, w1.y, w1.z, w1.w};
    float lb[8] = {lb0.x, lb0.y, lb0.z, lb0.w, lb1.x, lb1.y, lb1.z, lb1.w};

    __half2 o[4];
#pragma unroll
    for (int i = 0; i < 4; i++) {
        float t0 = d[2 * i]     * inv * lw[2 * i]     + lb[2 * i];
        float t1 = d[2 * i + 1] * inv * lw[2 * i + 1] + lb[2 * i + 1];
        t0 = (t0 >= 0.f) ? t0 : LEAKY * t0;
        t1 = (t1 >= 0.f) ? t1 : LEAKY * t1;
        o[i] = __floats2half2_rn(t0, t1);
    }
    *(uint4*)(out + (size_t)node * HID + f0) = *(uint4*)o;
}

// ---------------- per-graph mean pool (fp16 input) ----------------
__global__ void k_pool(const __half* __restrict__ h, const void* batch,
                       float* __restrict__ out) {
    int g = blockIdx.x;
    int is64 = g_is64;

    int lo = 0, hi = N_NODES;
    while (lo < hi) {
        int mid = (lo + hi) >> 1;
        if (load_idx(batch, mid, is64) < g) lo = mid + 1; else hi = mid;
    }
    int start = lo;
    hi = N_NODES;
    while (lo < hi) {
        int mid = (lo + hi) >> 1;
        if (load_idx(batch, mid, is64) < g + 1) lo = mid + 1; else hi = mid;
    }
    int end = lo;

    int t = threadIdx.x;
    float a0 = 0.f, a1 = 0.f, a2 = 0.f, a3 = 0.f;
    int i = start;
    for (; i + 3 < end; i += 4) {
        a0 += __half2float(h[(size_t)(i + 0) * HID + t]);
        a1 += __half2float(h[(size_t)(i + 1) * HID + t]);
        a2 += __half2float(h[(size_t)(i + 2) * HID + t]);
        a3 += __half2float(h[(size_t)(i + 3) * HID + t]);
    }
    for (; i < end; i++) a0 += __half2float(h[(size_t)i * HID + t]);
    float acc = (a0 + a1) + (a2 + a3);
    float cnt = (float)(end - start);
    out[(size_t)g * HID + t] = acc / fmaxf(cnt, 1.f);
}

// ---------------- launch ----------------
extern "C" void kernel_launch(void* const* d_in, const int* in_sizes, int n_in,
                              void* d_out, int out_size) {
    const float* x    = (const float*)d_in[0];
    const void*  edge = d_in[1];
    const void*  batch= d_in[2];
    const float* W1   = (const float*)d_in[3];
    const float* b1   = (const float*)d_in[4];
    const float* ln1w = (const float*)d_in[5];
    const float* ln1b = (const float*)d_in[6];
    const float* W2   = (const float*)d_in[7];
    const float* b2   = (const float*)d_in[8];
    const float* ln2w = (const float*)d_in[9];
    const float* ln2b = (const float*)d_in[10];
    float* out = (float*)d_out;

    __half *hA = nullptr, *hB = nullptr, *Wt1 = nullptr, *Wt2 = nullptr;
    cudaGetSymbolAddress((void**)&hA, g_h16A);
    cudaGetSymbolAddress((void**)&hB, g_h16B);
    cudaGetSymbolAddress((void**)&Wt1, g_Wt1);
    cudaGetSymbolAddress((void**)&Wt2, g_Wt2);

    static cudaStream_t s_side = nullptr;
    static cudaEvent_t  s_fork = nullptr, s_join = nullptr;
    static int s_ok = -1;
    if (s_ok < 0) {
        s_ok = 1;
        if (cudaStreamCreateWithFlags(&s_side, cudaStreamNonBlocking) != cudaSuccess) s_ok = 0;
        if (s_ok && cudaEventCreateWithFlags(&s_fork, cudaEventDisableTiming) != cudaSuccess) s_ok = 0;
        if (s_ok && cudaEventCreateWithFlags(&s_join, cudaEventDisableTiming) != cudaSuccess) s_ok = 0;
    }
    cudaStream_t side = s_ok ? s_side : (cudaStream_t)0;

    const int TB = 256;
    int gN = (N_NODES + TB - 1) / TB;
    int gE = (N_EDGES + TB - 1) / TB;

    dim3 gemmGrid((N_NODES + BM - 1) / BM, 256 / BN);
    int aggBlocks = (N_NODES * 32 + TB - 1) / TB;

    if (s_ok) {
        cudaEventRecord(s_fork, 0);
        cudaStreamWaitEvent(side, s_fork, 0);
    }

    // main stream: W1 convert, then GEMM1
    k_wconv<<<HID, HID>>>(W1, Wt1);
    k_gemm<float><<<gemmGrid, TB>>>(x, Wt1, hA, N_NODES);

    // side stream: CSR build (+ weights) + W2 convert
    k_detect_init<<<gN + 1, TB, 0, side>>>(edge, gN);
    k_count<<<gE, TB, 0, side>>>(edge);
    k_scan1<<<SCAN_NBLK, 1024, 0, side>>>();
    k_scan2<<<1, 32, 0, side>>>();
    k_scan3<<<gN, TB, 0, side>>>();
    k_scatter<<<gE, TB, 0, side>>>(edge);
    k_wconv<<<HID, HID, 0, side>>>(W2, Wt2);

    if (s_ok) {
        cudaEventRecord(s_join, side);
        cudaStreamWaitEvent(0, s_join, 0);
    }

    k_agg_ln<<<aggBlocks, TB>>>(hA, hB, b1, ln1w, ln1b);

    k_gemm<__half><<<gemmGrid, TB>>>(hB, Wt2, hA, N_NODES);
    k_agg_ln<<<aggBlocks, TB>>>(hA, hB, b2, ln2w, ln2b);

    k_pool<<<NUM_GRAPHS, HID>>>(hB, batch, out);
}

// round 14
// speedup vs baseline: 1.1376x; 1.0625x over previous
#include <cuda_runtime.h>
#include <cuda_fp16.h>
#include <math.h>
#include <stdint.h>

#define N_NODES   50000
#define N_EDGES   800000
#define HID       256
#define NUM_GRAPHS 512
#define LEAKY     0.01f
#define LN_EPS    1e-5f

#define SCAN_CH   2048
#define SCAN_NBLK ((N_NODES + SCAN_CH - 1) / SCAN_CH)   // 25

// ---------------- device scratch ----------------
__device__ int   g_is64;
__device__ int   g_deg[N_NODES];
__device__ float g_dinv[N_NODES];
__device__ int   g_rowptr[N_NODES + 1];
__device__ int   g_cursor[N_NODES];
__device__ int   g_csr_src[N_EDGES];
__device__ float g_csr_w[N_EDGES];
__device__ int   g_bsum[SCAN_NBLK];
__device__ int   g_boff[SCAN_NBLK];
__device__ __align__(16) __half g_h16A[(size_t)N_NODES * HID];  // GEMM out
__device__ __align__(16) __half g_h16B[(size_t)N_NODES * HID];  // agg out
__device__ __align__(16) __half g_Wt1[HID * HID];
__device__ __align__(16) __half g_Wt2[HID * HID];

__device__ __forceinline__ int load_idx(const void* p, long long i, int is64) {
    return is64 ? (int)((const long long*)p)[i] : ((const int*)p)[i];
}

__device__ __forceinline__ void load8h(const __half* p, float* f) {
    uint4 u = *(const uint4*)p;
    const __half2* hp = (const __half2*)&u;
#pragma unroll
    for (int i = 0; i < 4; i++) {
        float2 t = __half22float2(hp[i]);
        f[2 * i] = t.x; f[2 * i + 1] = t.y;
    }
}

// ---------------- W transpose + fp16 convert ----------------
__global__ void k_wconv(const float* __restrict__ W, __half* __restrict__ Wt) {
    int n = blockIdx.x;
    int k = threadIdx.x;
    Wt[n * HID + k] = __float2half_rn(W[(size_t)k * HID + n]);
}

// ---------------- fused: init deg + dtype detect ----------------
__global__ void k_detect_init(const void* edge, int gN) {
    if (blockIdx.x < gN) {
        int i = blockIdx.x * blockDim.x + threadIdx.x;
        if (i < N_NODES) g_deg[i] = 1;
        return;
    }
    __shared__ int any;
    if (threadIdx.x == 0) any = 0;
    __syncthreads();
    const int* w = (const int*)edge;
    int local = 0;
    for (int i = threadIdx.x; i < 1024; i += blockDim.x)
        if (w[2 * i + 1] != 0) local = 1;
    if (local) atomicOr(&any, 1);
    __syncthreads();
    if (threadIdx.x == 0) g_is64 = (any == 0) ? 1 : 0;
}

__global__ void k_count(const void* edge) {
    int e = blockIdx.x * blockDim.x + threadIdx.x;
    if (e >= N_EDGES) return;
    int is64 = g_is64;
    int d = load_idx(edge, (long long)N_EDGES + e, is64);
    atomicAdd(&g_deg[d], 1);
}

// ---------------- parallel 3-pass scan ----------------
__global__ void __launch_bounds__(1024) k_scan1() {
    __shared__ int wsum[32];
    int b    = blockIdx.x;
    int tid  = threadIdx.x;
    int lane = tid & 31;
    int wid  = tid >> 5;

    int i0 = b * SCAN_CH + tid * 2;
    int d0 = (i0     < N_NODES) ? g_deg[i0]     : 1;
    int d1 = (i0 + 1 < N_NODES) ? g_deg[i0 + 1] : 1;
    int v0 = (i0     < N_NODES) ? (d0 - 1) : 0;
    int v1 = (i0 + 1 < N_NODES) ? (d1 - 1) : 0;
    int v = v0 + v1;

    int x = v;
#pragma unroll
    for (int off = 1; off < 32; off <<= 1) {
        int t = __shfl_up_sync(0xffffffff, x, off);
        if (lane >= off) x += t;
    }
    if (lane == 31) wsum[wid] = x;
    __syncthreads();
    if (wid == 0) {
        int y = wsum[lane];
#pragma unroll
        for (int off = 1; off < 32; off <<= 1) {
            int t = __shfl_up_sync(0xffffffff, y, off);
            if (lane >= off) y += t;
        }
        wsum[lane] = y;
    }
    __syncthreads();

    int base = (wid ? wsum[wid - 1] : 0) + x - v;
    if (i0 < N_NODES) {
        g_rowptr[i0] = base;
        g_dinv[i0]   = rsqrtf((float)d0);
    }
    if (i0 + 1 < N_NODES) {
        g_rowptr[i0 + 1] = base + v0;
        g_dinv[i0 + 1]   = rsqrtf((float)d1);
    }
    if (tid == 0) g_bsum[b] = 0;
    __syncthreads();
    if (tid == 1023) g_bsum[b] = wsum[31];
}

__global__ void k_scan2() {
    int lane = threadIdx.x;
    int v = (lane < SCAN_NBLK) ? g_bsum[lane] : 0;
    int x = v;
#pragma unroll
    for (int off = 1; off < 32; off <<= 1) {
        int t = __shfl_up_sync(0xffffffff, x, off);
        if (lane >= off) x += t;
    }
    if (lane < SCAN_NBLK) g_boff[lane] = x - v;
    if (lane == 31) g_rowptr[N_NODES] = x;
}

__global__ void k_scan3() {
    int i = blockIdx.x * blockDim.x + threadIdx.x;
    if (i >= N_NODES) return;
    int off = g_boff[i / SCAN_CH];
    int r = g_rowptr[i] + off;
    g_rowptr[i] = r;
    g_cursor[i] = r;
}

__global__ void k_scatter(const void* edge) {
    int e = blockIdx.x * blockDim.x + threadIdx.x;
    if (e >= N_EDGES) return;
    int is64 = g_is64;
    int srce = load_idx(edge, e, is64);
    int dste = load_idx(edge, (long long)N_EDGES + e, is64);
    int pos = atomicAdd(&g_cursor[dste], 1);
    g_csr_src[pos] = srce;
    g_csr_w[pos]   = g_dinv[srce] * g_dinv[dste];
}

// ---------------- fp16 tensor-core GEMM: C[M,256](fp16) = A @ Wt^T -------
#define BM 128
#define BN 128
#define BK 16
#define KPAD 24

__device__ __forceinline__ void mma_f16(float* c, const uint32_t* a, const uint32_t* b) {
    asm volatile(
        "mma.sync.aligned.m16n8k16.row.col.f32.f16.f16.f32 "
        "{%0,%1,%2,%3}, {%4,%5,%6,%7}, {%8,%9}, {%0,%1,%2,%3};"
        : "+f"(c[0]), "+f"(c[1]), "+f"(c[2]), "+f"(c[3])
        : "r"(a[0]), "r"(a[1]), "r"(a[2]), "r"(a[3]), "r"(b[0]), "r"(b[1]));
}

__device__ __forceinline__ uint4 ldA8(const float* A, size_t off) {
    float4 f0 = *(const float4*)(A + off);
    float4 f1 = *(const float4*)(A + off + 4);
    __half2 h0 = __floats2half2_rn(f0.x, f0.y);
    __half2 h1 = __floats2half2_rn(f0.z, f0.w);
    __half2 h2 = __floats2half2_rn(f1.x, f1.y);
    __half2 h3 = __floats2half2_rn(f1.z, f1.w);
    uint4 r;
    r.x = *(uint32_t*)&h0; r.y = *(uint32_t*)&h1;
    r.z = *(uint32_t*)&h2; r.w = *(uint32_t*)&h3;
    return r;
}
__device__ __forceinline__ uint4 ldA8(const __half* A, size_t off) {
    return *(const uint4*)(A + off);
}

template <typename AT>
__global__ void __launch_bounds__(256)
k_gemm(const AT* __restrict__ A, const __half* __restrict__ Wt,
       __half* __restrict__ C, int M) {
    __shared__ __half As[2][BM][KPAD];
    __shared__ __half Bs[2][BN][KPAD];

    int tid  = threadIdx.x;
    int lane = tid & 31;
    int wid  = tid >> 5;
    int gid  = lane >> 2;
    int tig  = lane & 3;
    int wm = (wid & 1) * 64;
    int wn = (wid >> 1) * 32;
    int m0 = blockIdx.x * BM;
    int n0 = blockIdx.y * BN;

    int srow = tid >> 1;
    int sk8  = (tid & 1) * 8;

    float acc[4][4][4];
#pragma unroll
    for (int i = 0; i < 4; i++)
#pragma unroll
        for (int j = 0; j < 4; j++)
#pragma unroll
            for (int r = 0; r < 4; r++) acc[i][j][r] = 0.f;

    uint4 pa, pb;
    {
        int m = m0 + srow;
        pa = (m < M) ? ldA8(A, (size_t)m * 256 + sk8)
                     : make_uint4(0u, 0u, 0u, 0u);
        pb = *(const uint4*)&Wt[(size_t)(n0 + srow) * 256 + sk8];
    }
    *(uint4*)&As[0][srow][sk8] = pa;
    *(uint4*)&Bs[0][srow][sk8] = pb;
    __syncthreads();

    int buf = 0;
    for (int k0 = 0; k0 < 256; k0 += BK) {
        bool has_next = (k0 + BK) < 256;
        if (has_next) {
            int kb = k0 + BK;
            int m = m0 + srow;
            pa = (m < M) ? ldA8(A, (size_t)m * 256 + kb + sk8)
                         : make_uint4(0u, 0u, 0u, 0u);
            pb = *(const uint4*)&Wt[(size_t)(n0 + srow) * 256 + kb + sk8];
        }

        uint32_t af[4][4];
        uint32_t bf[4][2];
#pragma unroll
        for (int mt = 0; mt < 4; mt++) {
            int r0 = wm + mt * 16 + gid;
            af[mt][0] = *(const uint32_t*)&As[buf][r0][2 * tig];
            af[mt][1] = *(const uint32_t*)&As[buf][r0 + 8][2 * tig];
            af[mt][2] = *(const uint32_t*)&As[buf][r0][2 * tig + 8];
            af[mt][3] = *(const uint32_t*)&As[buf][r0 + 8][2 * tig + 8];
        }
#pragma unroll
        for (int nt = 0; nt < 4; nt++) {
            int c0 = wn + nt * 8 + gid;
            bf[nt][0] = *(const uint32_t*)&Bs[buf][c0][2 * tig];
            bf[nt][1] = *(const uint32_t*)&Bs[buf][c0][2 * tig + 8];
        }
#pragma unroll
        for (int mt = 0; mt < 4; mt++)
#pragma unroll
            for (int nt = 0; nt < 4; nt++)
                mma_f16(acc[mt][nt], af[mt], bf[nt]);

        if (has_next) {
            int nb = buf ^ 1;
            *(uint4*)&As[nb][srow][sk8] = pa;
            *(uint4*)&Bs[nb][srow][sk8] = pb;
            __syncthreads();
            buf = nb;
        }
    }

#pragma unroll
    for (int mt = 0; mt < 4; mt++) {
#pragma unroll
        for (int nt = 0; nt < 4; nt++) {
            int r0 = m0 + wm + mt * 16 + gid;
            int col = n0 + wn + nt * 8 + tig * 2;
            if (r0 < M)
                *(__half2*)&C[(size_t)r0 * 256 + col] =
                    __floats2half2_rn(acc[mt][nt][0], acc[mt][nt][1]);
            if (r0 + 8 < M)
                *(__half2*)&C[(size_t)(r0 + 8) * 256 + col] =
                    __floats2half2_rn(acc[mt][nt][2], acc[mt][nt][3]);
        }
    }
}

// ---------------- fused aggregate + bias + LayerNorm + LeakyReLU ----------
// fp16 in/out; 2-acc / 2-edge unroll (lean registers -> higher occupancy).
__global__ void __launch_bounds__(256)
k_agg_ln(const __half* __restrict__ h, __half* __restrict__ out,
         const float* __restrict__ bias,
         const float* __restrict__ lnw,
         const float* __restrict__ lnb) {
    int warp = (blockIdx.x * blockDim.x + threadIdx.x) >> 5;
    int lane = threadIdx.x & 31;
    if (warp >= N_NODES) return;
    int node = warp;
    int f0 = lane * 8;

    float di = g_dinv[node];
    float ws = di * di;

    float a0[8], a1[8];
    {
        float sf[8];
        load8h(h + (size_t)node * HID + f0, sf);
#pragma unroll
        for (int i = 0; i < 8; i++) { a0[i] = sf[i] * ws; a1[i] = 0.f; }
    }

    int beg = g_rowptr[node];
    int end = g_rowptr[node + 1];
    int e = beg;
    for (; e + 1 < end; e += 2) {
        int s0 = g_csr_src[e];
        int s1 = g_csr_src[e + 1];
        float w0 = g_csr_w[e];
        float w1 = g_csr_w[e + 1];
        float r0[8], r1[8];
        load8h(h + (size_t)s0 * HID + f0, r0);
        load8h(h + (size_t)s1 * HID + f0, r1);
#pragma unroll
        for (int i = 0; i < 8; i++) {
            a0[i] += r0[i] * w0;
            a1[i] += r1[i] * w1;
        }
    }
    if (e < end) {
        int s = g_csr_src[e];
        float wv = g_csr_w[e];
        float r[8];
        load8h(h + (size_t)s * HID + f0, r);
#pragma unroll
        for (int i = 0; i < 8; i++) a0[i] += r[i] * wv;
    }

    float a[8];
#pragma unroll
    for (int i = 0; i < 8; i++) a[i] = a0[i] + a1[i];

    float4 b0 = ((const float4*)bias)[lane * 2];
    float4 b1 = ((const float4*)bias)[lane * 2 + 1];
    a[0] += b0.x; a[1] += b0.y; a[2] += b0.z; a[3] += b0.w;
    a[4] += b1.x; a[5] += b1.y; a[6] += b1.z; a[7] += b1.w;

    float sum = 0.f;
#pragma unroll
    for (int i = 0; i < 8; i++) sum += a[i];
#pragma unroll
    for (int off = 16; off > 0; off >>= 1)
        sum += __shfl_xor_sync(0xffffffff, sum, off);
    float mu = sum * (1.0f / HID);

    float d[8], sq = 0.f;
#pragma unroll
    for (int i = 0; i < 8; i++) { d[i] = a[i] - mu; sq += d[i] * d[i]; }
#pragma unroll
    for (int off = 16; off > 0; off >>= 1)
        sq += __shfl_xor_sync(0xffffffff, sq, off);
    float inv = rsqrtf(sq * (1.0f / HID) + LN_EPS);

    float4 w0 = ((const float4*)lnw)[lane * 2];
    float4 w1 = ((const float4*)lnw)[lane * 2 + 1];
    float4 lb0 = ((const float4*)lnb)[lane * 2];
    float4 lb1 = ((const float4*)lnb)[lane * 2 + 1];
    float lw[8] = {w0.x, w0.y, w0.z, w0.w, w1.x, w1.y, w1.z, w1.w};
    float lb[8] = {lb0.x, lb0.y, lb0.z, lb0.w, lb1.x, lb1.y, lb1.z, lb1.w};

    __half2 o[4];
#pragma unroll
    for (int i = 0; i < 4; i++) {
        float t0 = d[2 * i]     * inv * lw[2 * i]     + lb[2 * i];
        float t1 = d[2 * i + 1] * inv * lw[2 * i + 1] + lb[2 * i + 1];
        t0 = (t0 >= 0.f) ? t0 : LEAKY * t0;
        t1 = (t1 >= 0.f) ? t1 : LEAKY * t1;
        o[i] = __floats2half2_rn(t0, t1);
    }
    *(uint4*)(out + (size_t)node * HID + f0) = *(uint4*)o;
}

// ---------------- per-graph mean pool (fp16 input, 8-way unroll) ---------
__global__ void k_pool(const __half* __restrict__ h, const void* batch,
                       float* __restrict__ out) {
    int g = blockIdx.x;
    int is64 = g_is64;

    int lo = 0, hi = N_NODES;
    while (lo < hi) {
        int mid = (lo + hi) >> 1;
        if (load_idx(batch, mid, is64) < g) lo = mid + 1; else hi = mid;
    }
    int start = lo;
    hi = N_NODES;
    while (lo < hi) {
        int mid = (lo + hi) >> 1;
        if (load_idx(batch, mid, is64) < g + 1) lo = mid + 1; else hi = mid;
    }
    int end = lo;

    int t = threadIdx.x;
    float acc8[8];
#pragma unroll
    for (int u = 0; u < 8; u++) acc8[u] = 0.f;
    int i = start;
    for (; i + 7 < end; i += 8) {
#pragma unroll
        for (int u = 0; u < 8; u++)
            acc8[u] += __half2float(h[(size_t)(i + u) * HID + t]);
    }
    for (; i < end; i++) acc8[0] += __half2float(h[(size_t)i * HID + t]);
    float acc = ((acc8[0] + acc8[1]) + (acc8[2] + acc8[3])) +
                ((acc8[4] + acc8[5]) + (acc8[6] + acc8[7]));
    float cnt = (float)(end - start);
    out[(size_t)g * HID + t] = acc / fmaxf(cnt, 1.f);
}

// ---------------- launch ----------------
extern "C" void kernel_launch(void* const* d_in, const int* in_sizes, int n_in,
                              void* d_out, int out_size) {
    const float* x    = (const float*)d_in[0];
    const void*  edge = d_in[1];
    const void*  batch= d_in[2];
    const float* W1   = (const float*)d_in[3];
    const float* b1   = (const float*)d_in[4];
    const float* ln1w = (const float*)d_in[5];
    const float* ln1b = (const float*)d_in[6];
    const float* W2   = (const float*)d_in[7];
    const float* b2   = (const float*)d_in[8];
    const float* ln2w = (const float*)d_in[9];
    const float* ln2b = (const float*)d_in[10];
    float* out = (float*)d_out;

    __half *hA = nullptr, *hB = nullptr, *Wt1 = nullptr, *Wt2 = nullptr;
    cudaGetSymbolAddress((void**)&hA, g_h16A);
    cudaGetSymbolAddress((void**)&hB, g_h16B);
    cudaGetSymbolAddress((void**)&Wt1, g_Wt1);
    cudaGetSymbolAddress((void**)&Wt2, g_Wt2);

    static cudaStream_t s_side = nullptr;
    static cudaEvent_t  s_fork = nullptr, s_join = nullptr;
    static int s_ok = -1;
    if (s_ok < 0) {
        s_ok = 1;
        if (cudaStreamCreateWithFlags(&s_side, cudaStreamNonBlocking) != cudaSuccess) s_ok = 0;
        if (s_ok && cudaEventCreateWithFlags(&s_fork, cudaEventDisableTiming) != cudaSuccess) s_ok = 0;
        if (s_ok && cudaEventCreateWithFlags(&s_join, cudaEventDisableTiming) != cudaSuccess) s_ok = 0;
    }
    cudaStream_t side = s_ok ? s_side : (cudaStream_t)0;

    const int TB = 256;
    int gN = (N_NODES + TB - 1) / TB;
    int gE = (N_EDGES + TB - 1) / TB;

    dim3 gemmGrid((N_NODES + BM - 1) / BM, 256 / BN);
    int aggBlocks = (N_NODES * 32 + TB - 1) / TB;

    if (s_ok) {
        cudaEventRecord(s_fork, 0);
        cudaStreamWaitEvent(side, s_fork, 0);
    }

    // main stream: W1 convert, then GEMM1
    k_wconv<<<HID, HID>>>(W1, Wt1);
    k_gemm<float><<<gemmGrid, TB>>>(x, Wt1, hA, N_NODES);

    // side stream: CSR build (+ weights) + W2 convert
    k_detect_init<<<gN + 1, TB, 0, side>>>(edge, gN);
    k_count<<<gE, TB, 0, side>>>(edge);
    k_scan1<<<SCAN_NBLK, 1024, 0, side>>>();
    k_scan2<<<1, 32, 0, side>>>();
    k_scan3<<<gN, TB, 0, side>>>();
    k_scatter<<<gE, TB, 0, side>>>(edge);
    k_wconv<<<HID, HID, 0, side>>>(W2, Wt2);

    if (s_ok) {
        cudaEventRecord(s_join, side);
        cudaStreamWaitEvent(0, s_join, 0);
    }

    k_agg_ln<<<aggBlocks, TB>>>(hA, hB, b1, ln1w, ln1b);

    k_gemm<__half><<<gemmGrid, TB>>>(hB, Wt2, hA, N_NODES);
    k_agg_ln<<<aggBlocks, TB>>>(hA, hB, b2, ln2w, ln2b);

    k_pool<<<NUM_GRAPHS, HID>>>(hB, batch, out);
}

// round 15
// speedup vs baseline: 1.1634x; 1.0227x over previous
#include <cuda_runtime.h>
#include <cuda_fp16.h>
#include <math.h>
#include <stdint.h>

#define N_NODES   50000
#define N_EDGES   800000
#define HID       256
#define NUM_GRAPHS 512
#define LEAKY     0.01f
#define LN_EPS    1e-5f

#define SCAN_CH   2048
#define SCAN_NBLK ((N_NODES + SCAN_CH - 1) / SCAN_CH)   // 25

// ---------------- device scratch ----------------
__device__ int   g_is64;
__device__ int   g_deg[N_NODES];
__device__ float g_dinv[N_NODES];
__device__ int   g_rowptr[N_NODES + 1];
__device__ int   g_cursor[N_NODES];
__device__ __align__(8) int   g_csr_src[N_EDGES];
__device__ __align__(8) float g_csr_w[N_EDGES];
__device__ int   g_bsum[SCAN_NBLK];
__device__ int   g_boff[SCAN_NBLK];
__device__ __align__(16) __half g_h16A[(size_t)N_NODES * HID];  // GEMM out
__device__ __align__(16) __half g_h16B[(size_t)N_NODES * HID];  // agg out
__device__ __align__(16) __half g_Wt1[HID * HID];
__device__ __align__(16) __half g_Wt2[HID * HID];

__device__ __forceinline__ int load_idx(const void* p, long long i, int is64) {
    return is64 ? (int)((const long long*)p)[i] : ((const int*)p)[i];
}

__device__ __forceinline__ void load8h(const __half* p, float* f) {
    uint4 u = *(const uint4*)p;
    const __half2* hp = (const __half2*)&u;
#pragma unroll
    for (int i = 0; i < 4; i++) {
        float2 t = __half22float2(hp[i]);
        f[2 * i] = t.x; f[2 * i + 1] = t.y;
    }
}

// ---------------- W transpose + fp16 convert ----------------
__global__ void k_wconv(const float* __restrict__ W, __half* __restrict__ Wt) {
    int n = blockIdx.x;
    int k = threadIdx.x;
    Wt[n * HID + k] = __float2half_rn(W[(size_t)k * HID + n]);
}

// ---------------- fused: init deg + dtype detect ----------------
__global__ void k_detect_init(const void* edge, int gN) {
    if (blockIdx.x < gN) {
        int i = blockIdx.x * blockDim.x + threadIdx.x;
        if (i < N_NODES) g_deg[i] = 1;
        return;
    }
    __shared__ int any;
    if (threadIdx.x == 0) any = 0;
    __syncthreads();
    const int* w = (const int*)edge;
    int local = 0;
    for (int i = threadIdx.x; i < 1024; i += blockDim.x)
        if (w[2 * i + 1] != 0) local = 1;
    if (local) atomicOr(&any, 1);
    __syncthreads();
    if (threadIdx.x == 0) g_is64 = (any == 0) ? 1 : 0;
}

__global__ void k_count(const void* edge) {
    int e = blockIdx.x * blockDim.x + threadIdx.x;
    if (e >= N_EDGES) return;
    int is64 = g_is64;
    int d = load_idx(edge, (long long)N_EDGES + e, is64);
    atomicAdd(&g_deg[d], 1);
}

// ---------------- parallel 3-pass scan ----------------
__global__ void __launch_bounds__(1024) k_scan1() {
    __shared__ int wsum[32];
    int b    = blockIdx.x;
    int tid  = threadIdx.x;
    int lane = tid & 31;
    int wid  = tid >> 5;

    int i0 = b * SCAN_CH + tid * 2;
    int d0 = (i0     < N_NODES) ? g_deg[i0]     : 1;
    int d1 = (i0 + 1 < N_NODES) ? g_deg[i0 + 1] : 1;
    int v0 = (i0     < N_NODES) ? (d0 - 1) : 0;
    int v1 = (i0 + 1 < N_NODES) ? (d1 - 1) : 0;
    int v = v0 + v1;

    int x = v;
#pragma unroll
    for (int off = 1; off < 32; off <<= 1) {
        int t = __shfl_up_sync(0xffffffff, x, off);
        if (lane >= off) x += t;
    }
    if (lane == 31) wsum[wid] = x;
    __syncthreads();
    if (wid == 0) {
        int y = wsum[lane];
#pragma unroll
        for (int off = 1; off < 32; off <<= 1) {
            int t = __shfl_up_sync(0xffffffff, y, off);
            if (lane >= off) y += t;
        }
        wsum[lane] = y;
    }
    __syncthreads();

    int base = (wid ? wsum[wid - 1] : 0) + x - v;
    if (i0 < N_NODES) {
        g_rowptr[i0] = base;
        g_dinv[i0]   = rsqrtf((float)d0);
    }
    if (i0 + 1 < N_NODES) {
        g_rowptr[i0 + 1] = base + v0;
        g_dinv[i0 + 1]   = rsqrtf((float)d1);
    }
    if (tid == 0) g_bsum[b] = 0;
    __syncthreads();
    if (tid == 1023) g_bsum[b] = wsum[31];
}

__global__ void k_scan2() {
    int lane = threadIdx.x;
    int v = (lane < SCAN_NBLK) ? g_bsum[lane] : 0;
    int x = v;
#pragma unroll
    for (int off = 1; off < 32; off <<= 1) {
        int t = __shfl_up_sync(0xffffffff, x, off);
        if (lane >= off) x += t;
    }
    if (lane < SCAN_NBLK) g_boff[lane] = x - v;
    if (lane == 31) g_rowptr[N_NODES] = x;
}

__global__ void k_scan3() {
    int i = blockIdx.x * blockDim.x + threadIdx.x;
    if (i >= N_NODES) return;
    int off = g_boff[i / SCAN_CH];
    int r = g_rowptr[i] + off;
    g_rowptr[i] = r;
    g_cursor[i] = r;
}

__global__ void k_scatter(const void* edge) {
    int e = blockIdx.x * blockDim.x + threadIdx.x;
    if (e >= N_EDGES) return;
    int is64 = g_is64;
    int srce = load_idx(edge, e, is64);
    int dste = load_idx(edge, (long long)N_EDGES + e, is64);
    int pos = atomicAdd(&g_cursor[dste], 1);
    g_csr_src[pos] = srce;
    g_csr_w[pos]   = g_dinv[srce] * g_dinv[dste];
}

// ---------------- fp16 tensor-core GEMM: C[M,256](fp16) = A @ Wt^T -------
#define BM 128
#define BN 128
#define BK 16
#define KPAD 24

__device__ __forceinline__ void mma_f16(float* c, const uint32_t* a, const uint32_t* b) {
    asm volatile(
        "mma.sync.aligned.m16n8k16.row.col.f32.f16.f16.f32 "
        "{%0,%1,%2,%3}, {%4,%5,%6,%7}, {%8,%9}, {%0,%1,%2,%3};"
        : "+f"(c[0]), "+f"(c[1]), "+f"(c[2]), "+f"(c[3])
        : "r"(a[0]), "r"(a[1]), "r"(a[2]), "r"(a[3]), "r"(b[0]), "r"(b[1]));
}

__device__ __forceinline__ uint4 ldA8(const float* A, size_t off) {
    float4 f0 = *(const float4*)(A + off);
    float4 f1 = *(const float4*)(A + off + 4);
    __half2 h0 = __floats2half2_rn(f0.x, f0.y);
    __half2 h1 = __floats2half2_rn(f0.z, f0.w);
    __half2 h2 = __floats2half2_rn(f1.x, f1.y);
    __half2 h3 = __floats2half2_rn(f1.z, f1.w);
    uint4 r;
    r.x = *(uint32_t*)&h0; r.y = *(uint32_t*)&h1;
    r.z = *(uint32_t*)&h2; r.w = *(uint32_t*)&h3;
    return r;
}
__device__ __forceinline__ uint4 ldA8(const __half* A, size_t off) {
    return *(const uint4*)(A + off);
}

template <typename AT>
__global__ void __launch_bounds__(256)
k_gemm(const AT* __restrict__ A, const __half* __restrict__ Wt,
       __half* __restrict__ C, int M) {
    __shared__ __half As[2][BM][KPAD];
    __shared__ __half Bs[2][BN][KPAD];

    int tid  = threadIdx.x;
    int lane = tid & 31;
    int wid  = tid >> 5;
    int gid  = lane >> 2;
    int tig  = lane & 3;
    int wm = (wid & 1) * 64;
    int wn = (wid >> 1) * 32;
    int m0 = blockIdx.x * BM;
    int n0 = blockIdx.y * BN;

    int srow = tid >> 1;
    int sk8  = (tid & 1) * 8;

    float acc[4][4][4];
#pragma unroll
    for (int i = 0; i < 4; i++)
#pragma unroll
        for (int j = 0; j < 4; j++)
#pragma unroll
            for (int r = 0; r < 4; r++) acc[i][j][r] = 0.f;

    uint4 pa, pb;
    {
        int m = m0 + srow;
        pa = (m < M) ? ldA8(A, (size_t)m * 256 + sk8)
                     : make_uint4(0u, 0u, 0u, 0u);
        pb = *(const uint4*)&Wt[(size_t)(n0 + srow) * 256 + sk8];
    }
    *(uint4*)&As[0][srow][sk8] = pa;
    *(uint4*)&Bs[0][srow][sk8] = pb;
    __syncthreads();

    int buf = 0;
    for (int k0 = 0; k0 < 256; k0 += BK) {
        bool has_next = (k0 + BK) < 256;
        if (has_next) {
            int kb = k0 + BK;
            int m = m0 + srow;
            pa = (m < M) ? ldA8(A, (size_t)m * 256 + kb + sk8)
                         : make_uint4(0u, 0u, 0u, 0u);
            pb = *(const uint4*)&Wt[(size_t)(n0 + srow) * 256 + kb + sk8];
        }

        uint32_t af[4][4];
        uint32_t bf[4][2];
#pragma unroll
        for (int mt = 0; mt < 4; mt++) {
            int r0 = wm + mt * 16 + gid;
            af[mt][0] = *(const uint32_t*)&As[buf][r0][2 * tig];
            af[mt][1] = *(const uint32_t*)&As[buf][r0 + 8][2 * tig];
            af[mt][2] = *(const uint32_t*)&As[buf][r0][2 * tig + 8];
            af[mt][3] = *(const uint32_t*)&As[buf][r0 + 8][2 * tig + 8];
        }
#pragma unroll
        for (int nt = 0; nt < 4; nt++) {
            int c0 = wn + nt * 8 + gid;
            bf[nt][0] = *(const uint32_t*)&Bs[buf][c0][2 * tig];
            bf[nt][1] = *(const uint32_t*)&Bs[buf][c0][2 * tig + 8];
        }
#pragma unroll
        for (int mt = 0; mt < 4; mt++)
#pragma unroll
            for (int nt = 0; nt < 4; nt++)
                mma_f16(acc[mt][nt], af[mt], bf[nt]);

        if (has_next) {
            int nb = buf ^ 1;
            *(uint4*)&As[nb][srow][sk8] = pa;
            *(uint4*)&Bs[nb][srow][sk8] = pb;
            __syncthreads();
            buf = nb;
        }
    }

#pragma unroll
    for (int mt = 0; mt < 4; mt++) {
#pragma unroll
        for (int nt = 0; nt < 4; nt++) {
            int r0 = m0 + wm + mt * 16 + gid;
            int col = n0 + wn + nt * 8 + tig * 2;
            if (r0 < M)
                *(__half2*)&C[(size_t)r0 * 256 + col] =
                    __floats2half2_rn(acc[mt][nt][0], acc[mt][nt][1]);
            if (r0 + 8 < M)
                *(__half2*)&C[(size_t)(r0 + 8) * 256 + col] =
                    __floats2half2_rn(acc[mt][nt][2], acc[mt][nt][3]);
        }
    }
}

// ---------------- fused aggregate + bias + LayerNorm + LeakyReLU ----------
// fp16 in/out; 2-acc / 2-edge unroll, paired int2/float2 CSR loads,
// capped registers for 6 CTAs/SM.
__global__ void __launch_bounds__(256, 6)
k_agg_ln(const __half* __restrict__ h, __half* __restrict__ out,
         const float* __restrict__ bias,
         const float* __restrict__ lnw,
         const float* __restrict__ lnb) {
    int warp = (blockIdx.x * blockDim.x + threadIdx.x) >> 5;
    int lane = threadIdx.x & 31;
    if (warp >= N_NODES) return;
    int node = warp;
    int f0 = lane * 8;

    float di = g_dinv[node];
    float ws = di * di;

    float a0[8], a1[8];
    {
        float sf[8];
        load8h(h + (size_t)node * HID + f0, sf);
#pragma unroll
        for (int i = 0; i < 8; i++) { a0[i] = sf[i] * ws; a1[i] = 0.f; }
    }

    int beg = g_rowptr[node];
    int end = g_rowptr[node + 1];
    int e = beg;
    // aligned 2-edge pairs (pairs starting at even e can use 64-bit loads;
    // handle a possible odd first edge to align)
    if ((e & 1) && e < end) {
        int s = g_csr_src[e];
        float wv = g_csr_w[e];
        float r[8];
        load8h(h + (size_t)s * HID + f0, r);
#pragma unroll
        for (int i = 0; i < 8; i++) a0[i] += r[i] * wv;
        e++;
    }
    for (; e + 1 < end; e += 2) {
        int2   s2 = *(const int2*)&g_csr_src[e];
        float2 w2 = *(const float2*)&g_csr_w[e];
        float r0[8], r1[8];
        load8h(h + (size_t)s2.x * HID + f0, r0);
        load8h(h + (size_t)s2.y * HID + f0, r1);
#pragma unroll
        for (int i = 0; i < 8; i++) {
            a0[i] += r0[i] * w2.x;
            a1[i] += r1[i] * w2.y;
        }
    }
    if (e < end) {
        int s = g_csr_src[e];
        float wv = g_csr_w[e];
        float r[8];
        load8h(h + (size_t)s * HID + f0, r);
#pragma unroll
        for (int i = 0; i < 8; i++) a0[i] += r[i] * wv;
    }

    float a[8];
#pragma unroll
    for (int i = 0; i < 8; i++) a[i] = a0[i] + a1[i];

    float4 b0 = ((const float4*)bias)[lane * 2];
    float4 b1 = ((const float4*)bias)[lane * 2 + 1];
    a[0] += b0.x; a[1] += b0.y; a[2] += b0.z; a[3] += b0.w;
    a[4] += b1.x; a[5] += b1.y; a[6] += b1.z; a[7] += b1.w;

    float sum = 0.f;
#pragma unroll
    for (int i = 0; i < 8; i++) sum += a[i];
#pragma unroll
    for (int off = 16; off > 0; off >>= 1)
        sum += __shfl_xor_sync(0xffffffff, sum, off);
    float mu = sum * (1.0f / HID);

    float d[8], sq = 0.f;
#pragma unroll
    for (int i = 0; i < 8; i++) { d[i] = a[i] - mu; sq += d[i] * d[i]; }
#pragma unroll
    for (int off = 16; off > 0; off >>= 1)
        sq += __shfl_xor_sync(0xffffffff, sq, off);
    float inv = rsqrtf(sq * (1.0f / HID) + LN_EPS);

    float4 w0 = ((const float4*)lnw)[lane * 2];
    float4 w1 = ((const float4*)lnw)[lane * 2 + 1];
    float4 lb0 = ((const float4*)lnb)[lane * 2];
    float4 lb1 = ((const float4*)lnb)[lane * 2 + 1];
    float lw[8] = {w0.x, w0.y, w0.z, w0.w, w1.x, w1.y, w1.z, w1.w};
    float lb[8] = {lb0.x, lb0.y, lb0.z, lb0.w, lb1.x, lb1.y, lb1.z, lb1.w};

    __half2 o[4];
#pragma unroll
    for (int i = 0; i < 4; i++) {
        float t0 = d[2 * i]     * inv * lw[2 * i]     + lb[2 * i];
        float t1 = d[2 * i + 1] * inv * lw[2 * i + 1] + lb[2 * i + 1];
        t0 = (t0 >= 0.f) ? t0 : LEAKY * t0;
        t1 = (t1 >= 0.f) ? t1 : LEAKY * t1;
        o[i] = __floats2half2_rn(t0, t1);
    }
    *(uint4*)(out + (size_t)node * HID + f0) = *(uint4*)o;
}

// ---------------- per-graph mean pool (fp16 input, 8-way unroll) ---------
__global__ void k_pool(const __half* __restrict__ h, const void* batch,
                       float* __restrict__ out) {
    int g = blockIdx.x;
    int is64 = g_is64;

    int lo = 0, hi = N_NODES;
    while (lo < hi) {
        int mid = (lo + hi) >> 1;
        if (load_idx(batch, mid, is64) < g) lo = mid + 1; else hi = mid;
    }
    int start = lo;
    hi = N_NODES;
    while (lo < hi) {
        int mid = (lo + hi) >> 1;
        if (load_idx(batch, mid, is64) < g + 1) lo = mid + 1; else hi = mid;
    }
    int end = lo;

    int t = threadIdx.x;
    float acc8[8];
#pragma unroll
    for (int u = 0; u < 8; u++) acc8[u] = 0.f;
    int i = start;
    for (; i + 7 < end; i += 8) {
#pragma unroll
        for (int u = 0; u < 8; u++)
            acc8[u] += __half2float(h[(size_t)(i + u) * HID + t]);
    }
    for (; i < end; i++) acc8[0] += __half2float(h[(size_t)i * HID + t]);
    float acc = ((acc8[0] + acc8[1]) + (acc8[2] + acc8[3])) +
                ((acc8[4] + acc8[5]) + (acc8[6] + acc8[7]));
    float cnt = (float)(end - start);
    out[(size_t)g * HID + t] = acc / fmaxf(cnt, 1.f);
}

// ---------------- launch ----------------
extern "C" void kernel_launch(void* const* d_in, const int* in_sizes, int n_in,
                              void* d_out, int out_size) {
    const float* x    = (const float*)d_in[0];
    const void*  edge = d_in[1];
    const void*  batch= d_in[2];
    const float* W1   = (const float*)d_in[3];
    const float* b1   = (const float*)d_in[4];
    const float* ln1w = (const float*)d_in[5];
    const float* ln1b = (const float*)d_in[6];
    const float* W2   = (const float*)d_in[7];
    const float* b2   = (const float*)d_in[8];
    const float* ln2w = (const float*)d_in[9];
    const float* ln2b = (const float*)d_in[10];
    float* out = (float*)d_out;

    __half *hA = nullptr, *hB = nullptr, *Wt1 = nullptr, *Wt2 = nullptr;
    cudaGetSymbolAddress((void**)&hA, g_h16A);
    cudaGetSymbolAddress((void**)&hB, g_h16B);
    cudaGetSymbolAddress((void**)&Wt1, g_Wt1);
    cudaGetSymbolAddress((void**)&Wt2, g_Wt2);

    static cudaStream_t s_side = nullptr;
    static cudaEvent_t  s_fork = nullptr, s_join = nullptr;
    static int s_ok = -1;
    if (s_ok < 0) {
        s_ok = 1;
        if (cudaStreamCreateWithFlags(&s_side, cudaStreamNonBlocking) != cudaSuccess) s_ok = 0;
        if (s_ok && cudaEventCreateWithFlags(&s_fork, cudaEventDisableTiming) != cudaSuccess) s_ok = 0;
        if (s_ok && cudaEventCreateWithFlags(&s_join, cudaEventDisableTiming) != cudaSuccess) s_ok = 0;
    }
    cudaStream_t side = s_ok ? s_side : (cudaStream_t)0;

    const int TB = 256;
    int gN = (N_NODES + TB - 1) / TB;
    int gE = (N_EDGES + TB - 1) / TB;

    dim3 gemmGrid((N_NODES + BM - 1) / BM, 256 / BN);
    int aggBlocks = (N_NODES * 32 + TB - 1) / TB;

    if (s_ok) {
        cudaEventRecord(s_fork, 0);
        cudaStreamWaitEvent(side, s_fork, 0);
    }

    // main stream: W1 convert, then GEMM1
    k_wconv<<<HID, HID>>>(W1, Wt1);
    k_gemm<float><<<gemmGrid, TB>>>(x, Wt1, hA, N_NODES);

    // side stream: CSR build (+ weights) + W2 convert
    k_detect_init<<<gN + 1, TB, 0, side>>>(edge, gN);
    k_count<<<gE, TB, 0, side>>>(edge);
    k_scan1<<<SCAN_NBLK, 1024, 0, side>>>();
    k_scan2<<<1, 32, 0, side>>>();
    k_scan3<<<gN, TB, 0, side>>>();
    k_scatter<<<gE, TB, 0, side>>>(edge);
    k_wconv<<<HID, HID, 0, side>>>(W2, Wt2);

    if (s_ok) {
        cudaEventRecord(s_join, side);
        cudaStreamWaitEvent(0, s_join, 0);
    }

    k_agg_ln<<<aggBlocks, TB>>>(hA, hB, b1, ln1w, ln1b);

    k_gemm<__half><<<gemmGrid, TB>>>(hB, Wt2, hA, N_NODES);
    k_agg_ln<<<aggBlocks, TB>>>(hA, hB, b2, ln2w, ln2b);

    k_pool<<<NUM_GRAPHS, HID>>>(hB, batch, out);
}